// round 14
// baseline (speedup 1.0000x reference)
#include <cuda_runtime.h>
#include <cuda_bf16.h>
#include <cuda_fp16.h>

#define NA 100000
#define NB 400000
#define NG 5000
#define SLOPEC 0.2f

// ----------------- device scratch (static; no allocations) -----------------
__device__ __align__(256) __half         g_Zhi[(size_t)(NA + 64) * 512];
__device__ __align__(256) float          g_hm[(size_t)(NA + 64) * 128];
__device__ __align__(256) float          g_U[NG * 256];
__device__ float         g_elu[NG * 2];
__device__ float         g_elh[NA * 2], g_er[NA * 2], g_eu[NA * 2];
__device__ unsigned      g_emaxkey[NA * 2];
__device__ __align__(16) float g_ehee[NB * 4];     // (eh0, eh1, ee0, ee1) bond order
__device__ __align__(8)  float g_ele[NB * 2];      // bond logits el (bond order)
__device__ int           g_deg[NA], g_cursor[NA];
__device__ __align__(8)  int2   g_bsrc[NB];        // CSR order: (bond, src)
__device__ __align__(16) float4 g_edata[NB];       // CSR order: logits
__device__ int2          g_range[NA];
__device__ int           g_bsum[128];
__device__ float         g_wAl[256], g_wAr[256], g_wBl[256];
__device__ __align__(256) __half g_WhT[128 * 512];  // [n][k] transposed, x0.5 folded, fp16
__device__ float         g_bnsum[128], g_bnsumsq[128];

// ----------------- helpers -----------------
__device__ __forceinline__ float lrelu(float x) { return x >= 0.f ? x : SLOPEC * x; }

__device__ __forceinline__ unsigned fkey(float f) {
    unsigned u = __float_as_uint(f);
    return (u & 0x80000000u) ? ~u : (u | 0x80000000u);
}
__device__ __forceinline__ float funkey(unsigned u) {
    u = (u & 0x80000000u) ? (u & 0x7fffffffu) : ~u;
    return __uint_as_float(u);
}
__device__ __forceinline__ float dot4(float4 a, float4 b) {
    return a.x * b.x + a.y * b.y + a.z * b.z + a.w * b.w;
}
__device__ __forceinline__ float wsum(float v) {
#pragma unroll
    for (int o = 16; o > 0; o >>= 1) v += __shfl_xor_sync(0xffffffffu, v, o);
    return v;
}

// store fp32 float4 -> fp16 (single plane, 8 bytes)
__device__ __forceinline__ void hstore(__half* ph, float4 v) {
    *(__half2*)(ph)     = __floats2half2_rn(v.x, v.y);
    *(__half2*)(ph + 2) = __floats2half2_rn(v.z, v.w);
}

// ----------------- merged prep -----------------
__global__ void k_prep(const float* __restrict__ Wa, const float* __restrict__ Wb,
                       const float* __restrict__ al, const float* __restrict__ ar) {
    int b = blockIdx.x, t = threadIdx.x;
    if (b < 391) {
        int i = b * 256 + t;
        if (i < NA) g_deg[i] = 0;
        if (b == 0 && t < 128) { g_bnsum[t] = 0.f; g_bnsumsq[t] = 0.f; }
    } else if (b < 397) {
        if (t < 128) {
            int m = (b - 391) >> 1, h = (b - 391) & 1;
            const float* W  = (m == 2) ? Wb : Wa;
            const float* at = (m == 1) ? ar : al;
            float s = 0.f;
            for (int d = 0; d < 128; d++) s += W[t * 256 + h * 128 + d] * at[h * 128 + d];
            float* o = (m == 0) ? g_wAl : (m == 1) ? g_wAr : g_wBl;
            o[h * 128 + t] = s;
        }
    } else {
        int idx = (b - 397) * 256 + t;   // 65536 = n*512 + k
        int n = idx >> 9, k = idx & 511;
        int s2 = k >> 7, i = k & 127, h = s2 & 1;
        const float* W = (s2 < 2) ? Wa : Wb;
        float x = 0.5f * W[i * 256 + h * 128 + n];
        g_WhT[idx] = __float2half(x);
    }
}

// ----------------- per-global projection + logit; 16 globals per block ----------
__global__ __launch_bounds__(256) void k_glob(const float* __restrict__ gf,
                                              const float* __restrict__ Wg,
                                              const float* __restrict__ al) {
    __shared__ float s_gf[16][128];
    __shared__ float s_elu[32];
    int g0 = blockIdx.x * 16, t = threadIdx.x, lane = t & 31;
    int head = t >> 7;
    if (t < 32) s_elu[t] = 0.f;
#pragma unroll
    for (int p = 0; p < 8; p++) {
        int e = t + p * 256;
        int j = e >> 7, d = e & 127;
        s_gf[j][d] = (g0 + j < NG) ? gf[(g0 + j) * 128 + d] : 0.f;
    }
    __syncthreads();
    float acc[16];
#pragma unroll
    for (int j = 0; j < 16; j++) acc[j] = 0.f;
    for (int i = 0; i < 128; i++) {
        float w = Wg[i * 256 + t];
#pragma unroll
        for (int j = 0; j < 16; j++) acc[j] += s_gf[j][i] * w;
    }
    float alt = al[t];
#pragma unroll
    for (int j = 0; j < 16; j++) {
        if (g0 + j < NG) g_U[(g0 + j) * 256 + t] = acc[j];
        float p = wsum(acc[j] * alt);
        if (lane == 0) atomicAdd(&s_elu[j * 2 + head], p);
    }
    __syncthreads();
    if (t < 32) {
        int j = t >> 1, h = t & 1;
        if (g0 + j < NG) g_elu[(g0 + j) * 2 + h] = s_elu[j * 2 + h];
    }
}

// ----------------- atom: streaming dot, register probes, 16 atoms/warp ----------
__global__ __launch_bounds__(256) void k_atom_dot(const float* __restrict__ af) {
    int lane = threadIdx.x & 31, wid = threadIdx.x >> 5;
    float4 pl0 = *(const float4*)&g_wAl[lane * 4];
    float4 pl1 = *(const float4*)&g_wAl[128 + lane * 4];
    float4 pr0 = *(const float4*)&g_wAr[lane * 4];
    float4 pr1 = *(const float4*)&g_wAr[128 + lane * 4];
    int a0 = (blockIdx.x * 8 + wid) * 16;
#pragma unroll 2
    for (int j = 0; j < 16; j++) {
        int a = a0 + j;
        if (a >= NA) return;
        float4 v = *(const float4*)&af[(size_t)a * 128 + lane * 4];
        float al0 = wsum(dot4(v, pl0));
        float al1 = wsum(dot4(v, pl1));
        float ar0 = wsum(dot4(v, pr0));
        float ar1 = wsum(dot4(v, pr1));
        if (lane == 0) {
            *(float2*)&g_elh[2 * a] = make_float2(al0, al1);
            *(float2*)&g_er[2 * a]  = make_float2(ar0, ar1);
        }
    }
}

// ----------------- bond: streaming dot, register probes, 16 bonds/warp ----------
__global__ __launch_bounds__(256) void k_bond_dot(const float* __restrict__ bf) {
    int lane = threadIdx.x & 31, wid = threadIdx.x >> 5;
    float4 p0 = *(const float4*)&g_wBl[lane * 4];
    float4 p1 = *(const float4*)&g_wBl[128 + lane * 4];
    int b0 = (blockIdx.x * 8 + wid) * 16;
#pragma unroll 4
    for (int j = 0; j < 16; j++) {
        int b = b0 + j;
        float4 v = *(const float4*)&bf[(size_t)b * 128 + lane * 4];
        float el0 = wsum(dot4(v, p0));
        float el1 = wsum(dot4(v, p1));
        if (lane == 0) *(float2*)&g_ele[2 * b] = make_float2(el0, el1);
    }
}

// ----------------- atom epilogue: thread-per-atom -----------------
__global__ void k_atom_epi(const int* __restrict__ gid) {
    int a = blockIdx.x * blockDim.x + threadIdx.x;
    if (a >= NA) return;
    float2 er = *(const float2*)&g_er[2 * a];
    int g = gid[a];
    float2 lu = *(const float2*)&g_elu[2 * g];
    float eu0 = lrelu(lu.x + er.x);
    float eu1 = lrelu(lu.y + er.y);
    *(float2*)&g_eu[2 * a] = make_float2(eu0, eu1);
    *(uint2*)&g_emaxkey[2 * a] = make_uint2(fkey(eu0), fkey(eu1));
}

__global__ void k_bond_epi(const int* __restrict__ src, const int* __restrict__ dst) {
    int b = blockIdx.x * blockDim.x + threadIdx.x;
    if (b >= NB) return;
    int s = src[b], d = dst[b];
    float2 el = *(const float2*)&g_ele[2 * b];
    float2 lh = *(const float2*)&g_elh[2 * s];
    float2 er = *(const float2*)&g_er[2 * d];
    float eh0 = lrelu(lh.x + er.x);
    float eh1 = lrelu(lh.y + er.y);
    float ee0 = lrelu(el.x + er.x);
    float ee1 = lrelu(el.y + er.y);
    *(float4*)&g_ehee[4 * b] = make_float4(eh0, eh1, ee0, ee1);
    atomicMax(&g_emaxkey[2 * d],     fkey(fmaxf(eh0, ee0)));
    atomicMax(&g_emaxkey[2 * d + 1], fkey(fmaxf(eh1, ee1)));
    atomicAdd(&g_deg[d], 1);
}

// ---- CSR build ----
__global__ void k_scan1() {
    __shared__ int s[1024];
    int t = threadIdx.x, idx = blockIdx.x * 1024 + t;
    s[t] = (idx < NA) ? g_deg[idx] : 0;
    __syncthreads();
    for (int o = 512; o > 0; o >>= 1) {
        if (t < o) s[t] += s[t + o];
        __syncthreads();
    }
    if (t == 0) g_bsum[blockIdx.x] = s[0];
}
__global__ void k_scan3(int nblk) {
    __shared__ int s[1024];
    __shared__ int s_boff;
    int t = threadIdx.x, idx = blockIdx.x * 1024 + t;
    int v = (idx < NA) ? g_deg[idx] : 0;
    s[t] = v;
    if (t < 32) {
        int acc = 0;
        for (int j = t; j < blockIdx.x; j += 32) acc += g_bsum[j];
        acc = wsum(acc);
        if (t == 0) s_boff = acc;
    }
    __syncthreads();
    for (int o = 1; o < 1024; o <<= 1) {
        int add = (t >= o) ? s[t - o] : 0;
        __syncthreads();
        s[t] += add;
        __syncthreads();
    }
    int excl = s[t] - v + s_boff;
    if (idx < NA) { g_range[idx] = make_int2(excl, excl + v); g_cursor[idx] = excl; }
}
__global__ void k_scatter(const int* __restrict__ src, const int* __restrict__ dst) {
    int b = blockIdx.x * blockDim.x + threadIdx.x;
    if (b >= NB) return;
    int pos = atomicAdd(&g_cursor[dst[b]], 1);
    g_bsrc[pos] = make_int2(b, src[b]);
    g_edata[pos] = *(const float4*)&g_ehee[4 * b];
}

// ---- gather pass A: atom-feature side -> Z cols [0,256) + hm base ----
__global__ __launch_bounds__(256) void k_gatherA(const float* __restrict__ af,
                                                 const int* __restrict__ gid) {
    int lane = threadIdx.x & 31;
    int a = blockIdx.x * 8 + (threadIdx.x >> 5);
    uint2 mk = *(const uint2*)&g_emaxkey[2 * a];
    float emax0 = funkey(mk.x), emax1 = funkey(mk.y);
    int2 rg = g_range[a];
    float4 aH0 = make_float4(0, 0, 0, 0), aH1 = aH0;
    float s0 = 0.f, s1 = 0.f;
    int i = rg.x, end = rg.y;
    for (; i + 4 <= end; i += 4) {
        int2 bs[4];
        float4 ev[4], avs[4];
#pragma unroll
        for (int j = 0; j < 4; j++) bs[j] = g_bsrc[i + j];
#pragma unroll
        for (int j = 0; j < 4; j++) ev[j] = g_edata[i + j];
#pragma unroll
        for (int j = 0; j < 4; j++)
            avs[j] = *(const float4*)&af[(size_t)bs[j].y * 128 + lane * 4];
#pragma unroll
        for (int j = 0; j < 4; j++) {
            float xh0 = __expf(ev[j].x - emax0), xh1 = __expf(ev[j].y - emax1);
            float xe0 = __expf(ev[j].z - emax0), xe1 = __expf(ev[j].w - emax1);
            s0 += xh0 + xe0; s1 += xh1 + xe1;
            aH0.x += xh0 * avs[j].x; aH0.y += xh0 * avs[j].y;
            aH0.z += xh0 * avs[j].z; aH0.w += xh0 * avs[j].w;
            aH1.x += xh1 * avs[j].x; aH1.y += xh1 * avs[j].y;
            aH1.z += xh1 * avs[j].z; aH1.w += xh1 * avs[j].w;
        }
    }
    for (; i < end; i++) {
        int2 bsx = g_bsrc[i];
        float4 ev = g_edata[i];
        float4 av = *(const float4*)&af[(size_t)bsx.y * 128 + lane * 4];
        float xh0 = __expf(ev.x - emax0), xh1 = __expf(ev.y - emax1);
        float xe0 = __expf(ev.z - emax0), xe1 = __expf(ev.w - emax1);
        s0 += xh0 + xe0; s1 += xh1 + xe1;
        aH0.x += xh0 * av.x; aH0.y += xh0 * av.y; aH0.z += xh0 * av.z; aH0.w += xh0 * av.w;
        aH1.x += xh1 * av.x; aH1.y += xh1 * av.y; aH1.z += xh1 * av.z; aH1.w += xh1 * av.w;
    }
    float2 euv = *(const float2*)&g_eu[2 * a];
    float xu0 = __expf(euv.x - emax0);
    float xu1 = __expf(euv.y - emax1);
    float inv0 = 1.f / (s0 + xu0);
    float inv1 = 1.f / (s1 + xu1);
    size_t zb = (size_t)a * 512 + lane * 4;
    hstore(&g_Zhi[zb],
           make_float4(aH0.x * inv0, aH0.y * inv0, aH0.z * inv0, aH0.w * inv0));
    hstore(&g_Zhi[zb + 128],
           make_float4(aH1.x * inv1, aH1.y * inv1, aH1.z * inv1, aH1.w * inv1));
    int g = gid[a];
    float4 u0 = *(const float4*)&g_U[g * 256 + lane * 4];
    float4 u1 = *(const float4*)&g_U[g * 256 + 128 + lane * 4];
    float au0 = 0.5f * xu0 * inv0, au1 = 0.5f * xu1 * inv1;
    float4 hb = make_float4(u0.x * au0 + u1.x * au1, u0.y * au0 + u1.y * au1,
                            u0.z * au0 + u1.z * au1, u0.w * au0 + u1.w * au1);
    *(float4*)&g_hm[(size_t)a * 128 + lane * 4] = hb;
}

// ---- gather pass B: bond-feature side -> Z cols [256,512) ----
__global__ __launch_bounds__(256) void k_gatherB(const float* __restrict__ bf) {
    int lane = threadIdx.x & 31;
    int a = blockIdx.x * 8 + (threadIdx.x >> 5);
    uint2 mk = *(const uint2*)&g_emaxkey[2 * a];
    float emax0 = funkey(mk.x), emax1 = funkey(mk.y);
    int2 rg = g_range[a];
    float4 aE0 = make_float4(0, 0, 0, 0), aE1 = aE0;
    float s0 = 0.f, s1 = 0.f;
    int i = rg.x, end = rg.y;
    for (; i + 4 <= end; i += 4) {
        int2 bs[4];
        float4 ev[4], bvs[4];
#pragma unroll
        for (int j = 0; j < 4; j++) bs[j] = g_bsrc[i + j];
#pragma unroll
        for (int j = 0; j < 4; j++) ev[j] = g_edata[i + j];
#pragma unroll
        for (int j = 0; j < 4; j++)
            bvs[j] = *(const float4*)&bf[(size_t)bs[j].x * 128 + lane * 4];
#pragma unroll
        for (int j = 0; j < 4; j++) {
            float xh0 = __expf(ev[j].x - emax0), xh1 = __expf(ev[j].y - emax1);
            float xe0 = __expf(ev[j].z - emax0), xe1 = __expf(ev[j].w - emax1);
            s0 += xh0 + xe0; s1 += xh1 + xe1;
            aE0.x += xe0 * bvs[j].x; aE0.y += xe0 * bvs[j].y;
            aE0.z += xe0 * bvs[j].z; aE0.w += xe0 * bvs[j].w;
            aE1.x += xe1 * bvs[j].x; aE1.y += xe1 * bvs[j].y;
            aE1.z += xe1 * bvs[j].z; aE1.w += xe1 * bvs[j].w;
        }
    }
    for (; i < end; i++) {
        int2 bsx = g_bsrc[i];
        float4 ev = g_edata[i];
        float4 bv = *(const float4*)&bf[(size_t)bsx.x * 128 + lane * 4];
        float xh0 = __expf(ev.x - emax0), xh1 = __expf(ev.y - emax1);
        float xe0 = __expf(ev.z - emax0), xe1 = __expf(ev.w - emax1);
        s0 += xh0 + xe0; s1 += xh1 + xe1;
        aE0.x += xe0 * bv.x; aE0.y += xe0 * bv.y; aE0.z += xe0 * bv.z; aE0.w += xe0 * bv.w;
        aE1.x += xe1 * bv.x; aE1.y += xe1 * bv.y; aE1.z += xe1 * bv.z; aE1.w += xe1 * bv.w;
    }
    float2 euv = *(const float2*)&g_eu[2 * a];
    float xu0 = __expf(euv.x - emax0);
    float xu1 = __expf(euv.y - emax1);
    float inv0 = 1.f / (s0 + xu0);
    float inv1 = 1.f / (s1 + xu1);
    size_t zb = (size_t)a * 512 + lane * 4;
    hstore(&g_Zhi[zb + 256],
           make_float4(aE0.x * inv0, aE0.y * inv0, aE0.z * inv0, aE0.w * inv0));
    hstore(&g_Zhi[zb + 384],
           make_float4(aE1.x * inv1, aE1.y * inv1, aE1.z * inv1, aE1.w * inv1));
}

// ---- single-term fp16 tensor-core GEMM, cp.async double buffered ----
#define STG_BYTES 27648
#define CP16(saddr, gptr) \
    asm volatile("cp.async.cg.shared.global [%0], [%1], 16;\n" :: "r"(saddr), "l"(gptr))

__device__ __forceinline__ void gemm_load_stage(unsigned char* dsm, int st, int row0,
                                                int k0, int tid) {
    unsigned sa = (unsigned)__cvta_generic_to_shared(dsm + st * STG_BYTES);
#pragma unroll
    for (int p = 0; p < 2; p++) {
        int e = tid + p * 256;
        int r = e >> 3, seg = e & 7;
        size_t go = (size_t)(row0 + r) * 512 + k0 + seg * 8;
        unsigned so = (unsigned)(r * 72 + seg * 8) * 2;
        CP16(sa + so, &g_Zhi[go]);
    }
#pragma unroll
    for (int p = 0; p < 4; p++) {
        int e = tid + p * 256;
        int n = e >> 3, seg = e & 7;
        size_t go = (size_t)n * 512 + k0 + seg * 8;
        unsigned so = (unsigned)(n * 72 + seg * 8) * 2;
        CP16(sa + 9216 + so, &g_WhT[go]);
    }
    asm volatile("cp.async.commit_group;\n" ::);
}

#define MMA_OP(c, A0, A1, A2, A3, B0, B1)                                              \
    asm volatile("mma.sync.aligned.m16n8k16.row.col.f32.f16.f16.f32 "                  \
                 "{%0,%1,%2,%3}, {%4,%5,%6,%7}, {%8,%9}, {%0,%1,%2,%3};"               \
                 : "+f"(c[0]), "+f"(c[1]), "+f"(c[2]), "+f"(c[3])                      \
                 : "r"(A0), "r"(A1), "r"(A2), "r"(A3), "r"(B0), "r"(B1))

__global__ __launch_bounds__(256) void k_gemm() {
    extern __shared__ __align__(16) unsigned char dsm[];
    __shared__ float s_sum[128], s_ssq[128];
    int tid = threadIdx.x;
    if (tid < 128) { s_sum[tid] = 0.f; s_ssq[tid] = 0.f; }
    int row0 = blockIdx.x * 64;
    int wid = tid >> 5, lane = tid & 31;
    int wm = wid & 3, wn = wid >> 2;
    int g = lane >> 2, t = lane & 3;
    float acc[8][4];
#pragma unroll
    for (int i = 0; i < 8; i++)
#pragma unroll
        for (int j = 0; j < 4; j++) acc[i][j] = 0.f;

    gemm_load_stage(dsm, 0, row0, 0, tid);
#pragma unroll 1
    for (int c = 0; c < 8; c++) {
        if (c < 7) {
            gemm_load_stage(dsm, (c + 1) & 1, row0, (c + 1) * 64, tid);
            asm volatile("cp.async.wait_group 1;\n" ::);
        } else {
            asm volatile("cp.async.wait_group 0;\n" ::);
        }
        __syncthreads();
        const __half* sAh = (const __half*)(dsm + (c & 1) * STG_BYTES);
        const __half* sBh = sAh + 4608;
        int m0 = wm * 16;
#pragma unroll
        for (int s = 0; s < 4; s++) {
            int ka = s * 16 + 2 * t;
            unsigned ah0 = *(const unsigned*)&sAh[(m0 + g) * 72 + ka];
            unsigned ah1 = *(const unsigned*)&sAh[(m0 + g + 8) * 72 + ka];
            unsigned ah2 = *(const unsigned*)&sAh[(m0 + g) * 72 + ka + 8];
            unsigned ah3 = *(const unsigned*)&sAh[(m0 + g + 8) * 72 + ka + 8];
#pragma unroll
            for (int nt = 0; nt < 8; nt++) {
                int n = wn * 64 + nt * 8 + g;
                unsigned bh0 = *(const unsigned*)&sBh[n * 72 + ka];
                unsigned bh1 = *(const unsigned*)&sBh[n * 72 + ka + 8];
                MMA_OP(acc[nt], ah0, ah1, ah2, ah3, bh0, bh1);
            }
        }
        __syncthreads();
    }
#pragma unroll
    for (int nt = 0; nt < 8; nt++) {
        int col = wn * 64 + nt * 8 + 2 * t;
        int r0 = row0 + wm * 16 + g;
        int r1 = r0 + 8;
        float sx = 0.f, sy = 0.f, qx = 0.f, qy = 0.f;
        if (r0 < NA) {
            float2 b = *(float2*)&g_hm[(size_t)r0 * 128 + col];
            float vx = b.x + acc[nt][0], vy = b.y + acc[nt][1];
            *(float2*)&g_hm[(size_t)r0 * 128 + col] = make_float2(vx, vy);
            sx += vx; sy += vy; qx += vx * vx; qy += vy * vy;
        }
        if (r1 < NA) {
            float2 b = *(float2*)&g_hm[(size_t)r1 * 128 + col];
            float vx = b.x + acc[nt][2], vy = b.y + acc[nt][3];
            *(float2*)&g_hm[(size_t)r1 * 128 + col] = make_float2(vx, vy);
            sx += vx; sy += vy; qx += vx * vx; qy += vy * vy;
        }
#pragma unroll
        for (int o = 4; o <= 16; o <<= 1) {
            sx += __shfl_xor_sync(0xffffffffu, sx, o);
            sy += __shfl_xor_sync(0xffffffffu, sy, o);
            qx += __shfl_xor_sync(0xffffffffu, qx, o);
            qy += __shfl_xor_sync(0xffffffffu, qy, o);
        }
        if (g == 0) {
            atomicAdd(&s_sum[col], sx);
            atomicAdd(&s_sum[col + 1], sy);
            atomicAdd(&s_ssq[col], qx);
            atomicAdd(&s_ssq[col + 1], qy);
        }
    }
    __syncthreads();
    if (tid < 128) {
        atomicAdd(&g_bnsum[tid], s_sum[tid]);
        atomicAdd(&g_bnsumsq[tid], s_ssq[tid]);
    }
}

// ---- batchnorm apply (scale/shift derived per block) + relu, float4 ----
__global__ __launch_bounds__(256) void k_bnapply(const float* __restrict__ gamma,
                                                 const float* __restrict__ beta,
                                                 float* __restrict__ out) {
    __shared__ float s_sc[128], s_sh[128];
    int t = threadIdx.x;
    if (t < 128) {
        float m = g_bnsum[t] / (float)NA;
        float var = g_bnsumsq[t] / (float)NA - m * m;
        float sc = gamma[t] / sqrtf(var + 1e-5f);
        s_sc[t] = sc;
        s_sh[t] = beta[t] - m * sc;
    }
    __syncthreads();
    int i = (blockIdx.x * blockDim.x + threadIdx.x) * 4;
    if (i < NA * 128) {
        float4 v = *(const float4*)&g_hm[i];
        int c = i & 127;
        v.x = fmaxf(v.x * s_sc[c]     + s_sh[c],     0.f);
        v.y = fmaxf(v.y * s_sc[c + 1] + s_sh[c + 1], 0.f);
        v.z = fmaxf(v.z * s_sc[c + 2] + s_sh[c + 2], 0.f);
        v.w = fmaxf(v.w * s_sc[c + 3] + s_sh[c + 3], 0.f);
        *(float4*)&out[i] = v;
    }
}

// ----------------- launch -----------------
extern "C" void kernel_launch(void* const* d_in, const int* in_sizes, int n_in,
                              void* d_out, int out_size) {
    const float* atom_feats   = (const float*)d_in[0];
    const float* bond_feats   = (const float*)d_in[1];
    const float* global_feats = (const float*)d_in[2];
    const float* W_atom       = (const float*)d_in[3];
    const float* W_bond       = (const float*)d_in[4];
    const float* W_global     = (const float*)d_in[5];
    const float* attn_l       = (const float*)d_in[6];
    const float* attn_r       = (const float*)d_in[7];
    const float* bn_gamma     = (const float*)d_in[8];
    const float* bn_beta      = (const float*)d_in[9];
    const int*   src          = (const int*)d_in[10];
    const int*   dst          = (const int*)d_in[11];
    const int*   gid          = (const int*)d_in[12];
    float* out = (float*)d_out;

    cudaFuncSetAttribute(k_gemm, cudaFuncAttributeMaxDynamicSharedMemorySize,
                         2 * STG_BYTES);

    const int nscan = (NA + 1023) / 1024;   // 98

    k_prep<<<653, 256>>>(W_atom, W_bond, attn_l, attn_r);
    k_glob<<<(NG + 15) / 16, 256>>>(global_feats, W_global, attn_l);
    k_atom_dot<<<(NA + 127) / 128, 256>>>(atom_feats);
    k_bond_dot<<<NB / 128, 256>>>(bond_feats);          // profiled slot #4 (control)
    k_atom_epi<<<(NA + 255) / 256, 256>>>(gid);
    k_bond_epi<<<(NB + 255) / 256, 256>>>(src, dst);
    k_scan1<<<nscan, 1024>>>();
    k_scan3<<<nscan, 1024>>>(nscan);
    k_scatter<<<(NB + 255) / 256, 256>>>(src, dst);
    k_gatherA<<<NA / 8, 256>>>(atom_feats, gid);
    k_gatherB<<<NA / 8, 256>>>(bond_feats);
    k_gemm<<<(NA + 63) / 64, 256, 2 * STG_BYTES>>>();
    k_bnapply<<<(NA * 128 / 4 + 255) / 256, 256>>>(bn_gamma, bn_beta, out);
}

// round 16
// speedup vs baseline: 1.0912x; 1.0912x over previous
#include <cuda_runtime.h>
#include <cuda_bf16.h>
#include <cuda_fp16.h>

#define NA 100000
#define NB 400000
#define NG 5000
#define SLOPEC 0.2f

// ----------------- device scratch (static; no allocations) -----------------
__device__ __align__(256) __half         g_Zhi[(size_t)(NA + 64) * 512];
__device__ __align__(256) float          g_hm[(size_t)(NA + 64) * 128];
__device__ __align__(256) float          g_U[NG * 256];
__device__ float         g_elu[NG * 2];
__device__ float         g_elh[NA * 2], g_er[NA * 2], g_eu[NA * 2];
__device__ unsigned      g_emaxkey[NA * 2];
__device__ __align__(16) float g_ehee[NB * 4];     // (eh0, eh1, ee0, ee1) bond order
__device__ __align__(8)  float g_ele[NB * 2];      // bond logits el (bond order)
__device__ int           g_deg[NA], g_cursor[NA];
__device__ __align__(8)  int2   g_bsrc[NB];        // CSR order: (bond, src)
__device__ __align__(16) float4 g_edata[NB];       // CSR order: logits
__device__ int2          g_range[NA];
__device__ int           g_bsum[128];
__device__ float         g_wAl[256], g_wAr[256], g_wBl[256];
__device__ __align__(256) __half g_WhT[128 * 512];  // [n][k] transposed, x0.5 folded, fp16
__device__ float         g_bnsum[128], g_bnsumsq[128];

// ----------------- helpers -----------------
__device__ __forceinline__ float lrelu(float x) { return x >= 0.f ? x : SLOPEC * x; }

__device__ __forceinline__ unsigned fkey(float f) {
    unsigned u = __float_as_uint(f);
    return (u & 0x80000000u) ? ~u : (u | 0x80000000u);
}
__device__ __forceinline__ float funkey(unsigned u) {
    u = (u & 0x80000000u) ? (u & 0x7fffffffu) : ~u;
    return __uint_as_float(u);
}
__device__ __forceinline__ float dot4(float4 a, float4 b) {
    return a.x * b.x + a.y * b.y + a.z * b.z + a.w * b.w;
}
__device__ __forceinline__ float wsum(float v) {
#pragma unroll
    for (int o = 16; o > 0; o >>= 1) v += __shfl_xor_sync(0xffffffffu, v, o);
    return v;
}

// store fp32 float4 -> fp16 (single plane, 8 bytes)
__device__ __forceinline__ void hstore(__half* ph, float4 v) {
    *(__half2*)(ph)     = __floats2half2_rn(v.x, v.y);
    *(__half2*)(ph + 2) = __floats2half2_rn(v.z, v.w);
}

// ----------------- merged prep -----------------
__global__ void k_prep(const float* __restrict__ Wa, const float* __restrict__ Wb,
                       const float* __restrict__ al, const float* __restrict__ ar) {
    int b = blockIdx.x, t = threadIdx.x;
    if (b < 391) {
        int i = b * 256 + t;
        if (i < NA) g_deg[i] = 0;
        if (b == 0 && t < 128) { g_bnsum[t] = 0.f; g_bnsumsq[t] = 0.f; }
    } else if (b < 397) {
        if (t < 128) {
            int m = (b - 391) >> 1, h = (b - 391) & 1;
            const float* W  = (m == 2) ? Wb : Wa;
            const float* at = (m == 1) ? ar : al;
            float s = 0.f;
            for (int d = 0; d < 128; d++) s += W[t * 256 + h * 128 + d] * at[h * 128 + d];
            float* o = (m == 0) ? g_wAl : (m == 1) ? g_wAr : g_wBl;
            o[h * 128 + t] = s;
        }
    } else {
        int idx = (b - 397) * 256 + t;   // 65536 = n*512 + k
        int n = idx >> 9, k = idx & 511;
        int s2 = k >> 7, i = k & 127, h = s2 & 1;
        const float* W = (s2 < 2) ? Wa : Wb;
        float x = 0.5f * W[i * 256 + h * 128 + n];
        g_WhT[idx] = __float2half(x);
    }
}

// ----------------- per-global projection + logit; 16 globals per block ----------
__global__ __launch_bounds__(256) void k_glob(const float* __restrict__ gf,
                                              const float* __restrict__ Wg,
                                              const float* __restrict__ al) {
    __shared__ float s_gf[16][128];
    __shared__ float s_elu[32];
    int g0 = blockIdx.x * 16, t = threadIdx.x, lane = t & 31;
    int head = t >> 7;
    if (t < 32) s_elu[t] = 0.f;
#pragma unroll
    for (int p = 0; p < 8; p++) {
        int e = t + p * 256;
        int j = e >> 7, d = e & 127;
        s_gf[j][d] = (g0 + j < NG) ? gf[(g0 + j) * 128 + d] : 0.f;
    }
    __syncthreads();
    float acc[16];
#pragma unroll
    for (int j = 0; j < 16; j++) acc[j] = 0.f;
    for (int i = 0; i < 128; i++) {
        float w = Wg[i * 256 + t];
#pragma unroll
        for (int j = 0; j < 16; j++) acc[j] += s_gf[j][i] * w;
    }
    float alt = al[t];
#pragma unroll
    for (int j = 0; j < 16; j++) {
        if (g0 + j < NG) g_U[(g0 + j) * 256 + t] = acc[j];
        float p = wsum(acc[j] * alt);
        if (lane == 0) atomicAdd(&s_elu[j * 2 + head], p);
    }
    __syncthreads();
    if (t < 32) {
        int j = t >> 1, h = t & 1;
        if (g0 + j < NG) g_elu[(g0 + j) * 2 + h] = s_elu[j * 2 + h];
    }
}

// ----------------- atom: streaming dot, register probes, 16 atoms/warp ----------
__global__ __launch_bounds__(256) void k_atom_dot(const float* __restrict__ af) {
    int lane = threadIdx.x & 31, wid = threadIdx.x >> 5;
    float4 pl0 = *(const float4*)&g_wAl[lane * 4];
    float4 pl1 = *(const float4*)&g_wAl[128 + lane * 4];
    float4 pr0 = *(const float4*)&g_wAr[lane * 4];
    float4 pr1 = *(const float4*)&g_wAr[128 + lane * 4];
    int a0 = (blockIdx.x * 8 + wid) * 16;
#pragma unroll 2
    for (int j = 0; j < 16; j++) {
        int a = a0 + j;
        if (a >= NA) return;
        float4 v = *(const float4*)&af[(size_t)a * 128 + lane * 4];
        float al0 = wsum(dot4(v, pl0));
        float al1 = wsum(dot4(v, pl1));
        float ar0 = wsum(dot4(v, pr0));
        float ar1 = wsum(dot4(v, pr1));
        if (lane == 0) {
            *(float2*)&g_elh[2 * a] = make_float2(al0, al1);
            *(float2*)&g_er[2 * a]  = make_float2(ar0, ar1);
        }
    }
}

// ----------------- bond: streaming dot, register probes, 16 bonds/warp ----------
__global__ __launch_bounds__(256) void k_bond_dot(const float* __restrict__ bf) {
    int lane = threadIdx.x & 31, wid = threadIdx.x >> 5;
    float4 p0 = *(const float4*)&g_wBl[lane * 4];
    float4 p1 = *(const float4*)&g_wBl[128 + lane * 4];
    int b0 = (blockIdx.x * 8 + wid) * 16;
#pragma unroll 4
    for (int j = 0; j < 16; j++) {
        int b = b0 + j;
        float4 v = *(const float4*)&bf[(size_t)b * 128 + lane * 4];
        float el0 = wsum(dot4(v, p0));
        float el1 = wsum(dot4(v, p1));
        if (lane == 0) *(float2*)&g_ele[2 * b] = make_float2(el0, el1);
    }
}

// ----------------- atom epilogue: thread-per-atom -----------------
__global__ void k_atom_epi(const int* __restrict__ gid) {
    int a = blockIdx.x * blockDim.x + threadIdx.x;
    if (a >= NA) return;
    float2 er = *(const float2*)&g_er[2 * a];
    int g = gid[a];
    float2 lu = *(const float2*)&g_elu[2 * g];
    float eu0 = lrelu(lu.x + er.x);
    float eu1 = lrelu(lu.y + er.y);
    *(float2*)&g_eu[2 * a] = make_float2(eu0, eu1);
    *(uint2*)&g_emaxkey[2 * a] = make_uint2(fkey(eu0), fkey(eu1));
}

__global__ void k_bond_epi(const int* __restrict__ src, const int* __restrict__ dst) {
    int b = blockIdx.x * blockDim.x + threadIdx.x;
    if (b >= NB) return;
    int s = src[b], d = dst[b];
    float2 el = *(const float2*)&g_ele[2 * b];
    float2 lh = *(const float2*)&g_elh[2 * s];
    float2 er = *(const float2*)&g_er[2 * d];
    float eh0 = lrelu(lh.x + er.x);
    float eh1 = lrelu(lh.y + er.y);
    float ee0 = lrelu(el.x + er.x);
    float ee1 = lrelu(el.y + er.y);
    *(float4*)&g_ehee[4 * b] = make_float4(eh0, eh1, ee0, ee1);
    atomicMax(&g_emaxkey[2 * d],     fkey(fmaxf(eh0, ee0)));
    atomicMax(&g_emaxkey[2 * d + 1], fkey(fmaxf(eh1, ee1)));
    atomicAdd(&g_deg[d], 1);
}

// ---- CSR build ----
__global__ void k_scan1() {
    __shared__ int s[1024];
    int t = threadIdx.x, idx = blockIdx.x * 1024 + t;
    s[t] = (idx < NA) ? g_deg[idx] : 0;
    __syncthreads();
    for (int o = 512; o > 0; o >>= 1) {
        if (t < o) s[t] += s[t + o];
        __syncthreads();
    }
    if (t == 0) g_bsum[blockIdx.x] = s[0];
}
__global__ void k_scan3(int nblk) {
    __shared__ int s[1024];
    __shared__ int s_boff;
    int t = threadIdx.x, idx = blockIdx.x * 1024 + t;
    int v = (idx < NA) ? g_deg[idx] : 0;
    s[t] = v;
    if (t < 32) {
        int acc = 0;
        for (int j = t; j < blockIdx.x; j += 32) acc += g_bsum[j];
        acc = wsum(acc);
        if (t == 0) s_boff = acc;
    }
    __syncthreads();
    for (int o = 1; o < 1024; o <<= 1) {
        int add = (t >= o) ? s[t - o] : 0;
        __syncthreads();
        s[t] += add;
        __syncthreads();
    }
    int excl = s[t] - v + s_boff;
    if (idx < NA) { g_range[idx] = make_int2(excl, excl + v); g_cursor[idx] = excl; }
}
__global__ void k_scatter(const int* __restrict__ src, const int* __restrict__ dst) {
    int b = blockIdx.x * blockDim.x + threadIdx.x;
    if (b >= NB) return;
    int pos = atomicAdd(&g_cursor[dst[b]], 1);
    g_bsrc[pos] = make_int2(b, src[b]);
    g_edata[pos] = *(const float4*)&g_ehee[4 * b];
}

// ---- gather: combined warp-per-atom; bf via streaming loads (__ldcs) ----
__global__ __launch_bounds__(256) void k_gather(const float* __restrict__ af,
                                                const float* __restrict__ bf,
                                                const int* __restrict__ gid) {
    int lane = threadIdx.x & 31;
    int a = blockIdx.x * 8 + (threadIdx.x >> 5);
    uint2 mk = *(const uint2*)&g_emaxkey[2 * a];
    float emax0 = funkey(mk.x), emax1 = funkey(mk.y);
    int2 rg = g_range[a];
    float4 aH0 = make_float4(0, 0, 0, 0), aH1 = aH0, aE0 = aH0, aE1 = aH0;
    float s0 = 0.f, s1 = 0.f;
    int i = rg.x, end = rg.y;
    for (; i + 4 <= end; i += 4) {
        int2 bs[4];
        float4 ev[4], avs[4], bvs[4];
#pragma unroll
        for (int j = 0; j < 4; j++) bs[j] = g_bsrc[i + j];
#pragma unroll
        for (int j = 0; j < 4; j++) ev[j] = g_edata[i + j];
#pragma unroll
        for (int j = 0; j < 4; j++) {
            avs[j] = *(const float4*)&af[(size_t)bs[j].y * 128 + lane * 4];
            bvs[j] = __ldcs((const float4*)&bf[(size_t)bs[j].x * 128 + lane * 4]);
        }
#pragma unroll
        for (int j = 0; j < 4; j++) {
            float xh0 = __expf(ev[j].x - emax0), xh1 = __expf(ev[j].y - emax1);
            float xe0 = __expf(ev[j].z - emax0), xe1 = __expf(ev[j].w - emax1);
            s0 += xh0 + xe0; s1 += xh1 + xe1;
            aH0.x += xh0 * avs[j].x; aH0.y += xh0 * avs[j].y;
            aH0.z += xh0 * avs[j].z; aH0.w += xh0 * avs[j].w;
            aH1.x += xh1 * avs[j].x; aH1.y += xh1 * avs[j].y;
            aH1.z += xh1 * avs[j].z; aH1.w += xh1 * avs[j].w;
            aE0.x += xe0 * bvs[j].x; aE0.y += xe0 * bvs[j].y;
            aE0.z += xe0 * bvs[j].z; aE0.w += xe0 * bvs[j].w;
            aE1.x += xe1 * bvs[j].x; aE1.y += xe1 * bvs[j].y;
            aE1.z += xe1 * bvs[j].z; aE1.w += xe1 * bvs[j].w;
        }
    }
    for (; i < end; i++) {
        int2 bsx = g_bsrc[i];
        float4 ev = g_edata[i];
        float4 av = *(const float4*)&af[(size_t)bsx.y * 128 + lane * 4];
        float4 bv = __ldcs((const float4*)&bf[(size_t)bsx.x * 128 + lane * 4]);
        float xh0 = __expf(ev.x - emax0), xh1 = __expf(ev.y - emax1);
        float xe0 = __expf(ev.z - emax0), xe1 = __expf(ev.w - emax1);
        s0 += xh0 + xe0; s1 += xh1 + xe1;
        aH0.x += xh0 * av.x; aH0.y += xh0 * av.y; aH0.z += xh0 * av.z; aH0.w += xh0 * av.w;
        aH1.x += xh1 * av.x; aH1.y += xh1 * av.y; aH1.z += xh1 * av.z; aH1.w += xh1 * av.w;
        aE0.x += xe0 * bv.x; aE0.y += xe0 * bv.y; aE0.z += xe0 * bv.z; aE0.w += xe0 * bv.w;
        aE1.x += xe1 * bv.x; aE1.y += xe1 * bv.y; aE1.z += xe1 * bv.z; aE1.w += xe1 * bv.w;
    }
    float2 euv = *(const float2*)&g_eu[2 * a];
    float xu0 = __expf(euv.x - emax0);
    float xu1 = __expf(euv.y - emax1);
    float inv0 = 1.f / (s0 + xu0);
    float inv1 = 1.f / (s1 + xu1);
    size_t zb = (size_t)a * 512 + lane * 4;
    hstore(&g_Zhi[zb],
           make_float4(aH0.x * inv0, aH0.y * inv0, aH0.z * inv0, aH0.w * inv0));
    hstore(&g_Zhi[zb + 128],
           make_float4(aH1.x * inv1, aH1.y * inv1, aH1.z * inv1, aH1.w * inv1));
    hstore(&g_Zhi[zb + 256],
           make_float4(aE0.x * inv0, aE0.y * inv0, aE0.z * inv0, aE0.w * inv0));
    hstore(&g_Zhi[zb + 384],
           make_float4(aE1.x * inv1, aE1.y * inv1, aE1.z * inv1, aE1.w * inv1));
    int g = gid[a];
    float4 u0 = *(const float4*)&g_U[g * 256 + lane * 4];
    float4 u1 = *(const float4*)&g_U[g * 256 + 128 + lane * 4];
    float au0 = 0.5f * xu0 * inv0, au1 = 0.5f * xu1 * inv1;
    float4 hb = make_float4(u0.x * au0 + u1.x * au1, u0.y * au0 + u1.y * au1,
                            u0.z * au0 + u1.z * au1, u0.w * au0 + u1.w * au1);
    *(float4*)&g_hm[(size_t)a * 128 + lane * 4] = hb;
}

// ---- single-term fp16 tensor-core GEMM, cp.async double buffered ----
#define STG_BYTES 27648
#define CP16(saddr, gptr) \
    asm volatile("cp.async.cg.shared.global [%0], [%1], 16;\n" :: "r"(saddr), "l"(gptr))

__device__ __forceinline__ void gemm_load_stage(unsigned char* dsm, int st, int row0,
                                                int k0, int tid) {
    unsigned sa = (unsigned)__cvta_generic_to_shared(dsm + st * STG_BYTES);
#pragma unroll
    for (int p = 0; p < 2; p++) {
        int e = tid + p * 256;
        int r = e >> 3, seg = e & 7;
        size_t go = (size_t)(row0 + r) * 512 + k0 + seg * 8;
        unsigned so = (unsigned)(r * 72 + seg * 8) * 2;
        CP16(sa + so, &g_Zhi[go]);
    }
#pragma unroll
    for (int p = 0; p < 4; p++) {
        int e = tid + p * 256;
        int n = e >> 3, seg = e & 7;
        size_t go = (size_t)n * 512 + k0 + seg * 8;
        unsigned so = (unsigned)(n * 72 + seg * 8) * 2;
        CP16(sa + 9216 + so, &g_WhT[go]);
    }
    asm volatile("cp.async.commit_group;\n" ::);
}

#define MMA_OP(c, A0, A1, A2, A3, B0, B1)                                              \
    asm volatile("mma.sync.aligned.m16n8k16.row.col.f32.f16.f16.f32 "                  \
                 "{%0,%1,%2,%3}, {%4,%5,%6,%7}, {%8,%9}, {%0,%1,%2,%3};"               \
                 : "+f"(c[0]), "+f"(c[1]), "+f"(c[2]), "+f"(c[3])                      \
                 : "r"(A0), "r"(A1), "r"(A2), "r"(A3), "r"(B0), "r"(B1))

__global__ __launch_bounds__(256) void k_gemm() {
    extern __shared__ __align__(16) unsigned char dsm[];
    __shared__ float s_sum[128], s_ssq[128];
    int tid = threadIdx.x;
    if (tid < 128) { s_sum[tid] = 0.f; s_ssq[tid] = 0.f; }
    int row0 = blockIdx.x * 64;
    int wid = tid >> 5, lane = tid & 31;
    int wm = wid & 3, wn = wid >> 2;
    int g = lane >> 2, t = lane & 3;
    float acc[8][4];
#pragma unroll
    for (int i = 0; i < 8; i++)
#pragma unroll
        for (int j = 0; j < 4; j++) acc[i][j] = 0.f;

    gemm_load_stage(dsm, 0, row0, 0, tid);
#pragma unroll 1
    for (int c = 0; c < 8; c++) {
        if (c < 7) {
            gemm_load_stage(dsm, (c + 1) & 1, row0, (c + 1) * 64, tid);
            asm volatile("cp.async.wait_group 1;\n" ::);
        } else {
            asm volatile("cp.async.wait_group 0;\n" ::);
        }
        __syncthreads();
        const __half* sAh = (const __half*)(dsm + (c & 1) * STG_BYTES);
        const __half* sBh = sAh + 4608;
        int m0 = wm * 16;
#pragma unroll
        for (int s = 0; s < 4; s++) {
            int ka = s * 16 + 2 * t;
            unsigned ah0 = *(const unsigned*)&sAh[(m0 + g) * 72 + ka];
            unsigned ah1 = *(const unsigned*)&sAh[(m0 + g + 8) * 72 + ka];
            unsigned ah2 = *(const unsigned*)&sAh[(m0 + g) * 72 + ka + 8];
            unsigned ah3 = *(const unsigned*)&sAh[(m0 + g + 8) * 72 + ka + 8];
#pragma unroll
            for (int nt = 0; nt < 8; nt++) {
                int n = wn * 64 + nt * 8 + g;
                unsigned bh0 = *(const unsigned*)&sBh[n * 72 + ka];
                unsigned bh1 = *(const unsigned*)&sBh[n * 72 + ka + 8];
                MMA_OP(acc[nt], ah0, ah1, ah2, ah3, bh0, bh1);
            }
        }
        __syncthreads();
    }
#pragma unroll
    for (int nt = 0; nt < 8; nt++) {
        int col = wn * 64 + nt * 8 + 2 * t;
        int r0 = row0 + wm * 16 + g;
        int r1 = r0 + 8;
        float sx = 0.f, sy = 0.f, qx = 0.f, qy = 0.f;
        if (r0 < NA) {
            float2 b = *(float2*)&g_hm[(size_t)r0 * 128 + col];
            float vx = b.x + acc[nt][0], vy = b.y + acc[nt][1];
            *(float2*)&g_hm[(size_t)r0 * 128 + col] = make_float2(vx, vy);
            sx += vx; sy += vy; qx += vx * vx; qy += vy * vy;
        }
        if (r1 < NA) {
            float2 b = *(float2*)&g_hm[(size_t)r1 * 128 + col];
            float vx = b.x + acc[nt][2], vy = b.y + acc[nt][3];
            *(float2*)&g_hm[(size_t)r1 * 128 + col] = make_float2(vx, vy);
            sx += vx; sy += vy; qx += vx * vx; qy += vy * vy;
        }
#pragma unroll
        for (int o = 4; o <= 16; o <<= 1) {
            sx += __shfl_xor_sync(0xffffffffu, sx, o);
            sy += __shfl_xor_sync(0xffffffffu, sy, o);
            qx += __shfl_xor_sync(0xffffffffu, qx, o);
            qy += __shfl_xor_sync(0xffffffffu, qy, o);
        }
        if (g == 0) {
            atomicAdd(&s_sum[col], sx);
            atomicAdd(&s_sum[col + 1], sy);
            atomicAdd(&s_ssq[col], qx);
            atomicAdd(&s_ssq[col + 1], qy);
        }
    }
    __syncthreads();
    if (tid < 128) {
        atomicAdd(&g_bnsum[tid], s_sum[tid]);
        atomicAdd(&g_bnsumsq[tid], s_ssq[tid]);
    }
}

// ---- batchnorm apply (scale/shift derived per block) + relu, float4 ----
__global__ __launch_bounds__(256) void k_bnapply(const float* __restrict__ gamma,
                                                 const float* __restrict__ beta,
                                                 float* __restrict__ out) {
    __shared__ float s_sc[128], s_sh[128];
    int t = threadIdx.x;
    if (t < 128) {
        float m = g_bnsum[t] / (float)NA;
        float var = g_bnsumsq[t] / (float)NA - m * m;
        float sc = gamma[t] / sqrtf(var + 1e-5f);
        s_sc[t] = sc;
        s_sh[t] = beta[t] - m * sc;
    }
    __syncthreads();
    int i = (blockIdx.x * blockDim.x + threadIdx.x) * 4;
    if (i < NA * 128) {
        float4 v = *(const float4*)&g_hm[i];
        int c = i & 127;
        v.x = fmaxf(v.x * s_sc[c]     + s_sh[c],     0.f);
        v.y = fmaxf(v.y * s_sc[c + 1] + s_sh[c + 1], 0.f);
        v.z = fmaxf(v.z * s_sc[c + 2] + s_sh[c + 2], 0.f);
        v.w = fmaxf(v.w * s_sc[c + 3] + s_sh[c + 3], 0.f);
        *(float4*)&out[i] = v;
    }
}

// ----------------- launch -----------------
extern "C" void kernel_launch(void* const* d_in, const int* in_sizes, int n_in,
                              void* d_out, int out_size) {
    const float* atom_feats   = (const float*)d_in[0];
    const float* bond_feats   = (const float*)d_in[1];
    const float* global_feats = (const float*)d_in[2];
    const float* W_atom       = (const float*)d_in[3];
    const float* W_bond       = (const float*)d_in[4];
    const float* W_global     = (const float*)d_in[5];
    const float* attn_l       = (const float*)d_in[6];
    const float* attn_r       = (const float*)d_in[7];
    const float* bn_gamma     = (const float*)d_in[8];
    const float* bn_beta      = (const float*)d_in[9];
    const int*   src          = (const int*)d_in[10];
    const int*   dst          = (const int*)d_in[11];
    const int*   gid          = (const int*)d_in[12];
    float* out = (float*)d_out;

    cudaFuncSetAttribute(k_gemm, cudaFuncAttributeMaxDynamicSharedMemorySize,
                         2 * STG_BYTES);

    const int nscan = (NA + 1023) / 1024;   // 98

    k_prep<<<653, 256>>>(W_atom, W_bond, attn_l, attn_r);
    k_glob<<<(NG + 15) / 16, 256>>>(global_feats, W_global, attn_l);
    k_atom_dot<<<(NA + 127) / 128, 256>>>(atom_feats);
    k_bond_dot<<<NB / 128, 256>>>(bond_feats);          // profiled slot #4 (control)
    k_atom_epi<<<(NA + 255) / 256, 256>>>(gid);
    k_bond_epi<<<(NB + 255) / 256, 256>>>(src, dst);
    k_scan1<<<nscan, 1024>>>();
    k_scan3<<<nscan, 1024>>>(nscan);
    k_scatter<<<(NB + 255) / 256, 256>>>(src, dst);
    k_gather<<<NA / 8, 256>>>(atom_feats, bond_feats, gid);
    k_gemm<<<(NA + 63) / 64, 256, 2 * STG_BYTES>>>();
    k_bnapply<<<(NA * 128 / 4 + 255) / 256, 256>>>(bn_gamma, bn_beta, out);
}